// round 1
// baseline (speedup 1.0000x reference)
#include <cuda_runtime.h>
#include <math.h>
#include <float.h>

// Problem constants
#define TT   512
#define BB   8
#define DD   512
#define HH   8
#define DHH  64
#define RR   1023          // 2T-1 distinct relative distances
#define BHN  64            // BB*HH
#define MROWS 4096         // TT*BB

// ---------------- scratch (static device globals; no allocation) -------------
__device__ float g_q[BHN * TT * DHH];      // [b*8+h][t][dh]
__device__ float g_k[BHN * TT * DHH];
__device__ float g_v[BHN * TT * DHH];
__device__ float g_rpe[RR * DD];           // [r][h*64+dh], r = (i-j)+511
__device__ float g_uk[BHN * TT];           // pos_u . k  per (b,h,j)
__device__ float g_vr[RR * HH];            // pos_v . rpe per (r,h)
__device__ float g_ao[MROWS * DD];         // attention output, (t,b,d) row-major

// ============================================================================
// Kernel 1: QKV GEMM.  C(M=4096,N=1536) = x(4096,512) @ W_qkv(512,1536)
// scatter into g_q/g_k/g_v with layout [b,h,t,dh]
// 64x64 tile, BK=16, 256 threads, 4x4 per thread.
// ============================================================================
__global__ void qkv_gemm_kernel(const float* __restrict__ x,
                                const float* __restrict__ W) {
    __shared__ float As[16 * 68];   // [k][m], padded
    __shared__ float Bs[16 * 64];   // [k][n]
    const int m0 = blockIdx.y * 64;
    const int n0 = blockIdx.x * 64;
    const int t  = threadIdx.x;
    const int tyy = t >> 4, txx = t & 15;
    const int arow = t >> 2, aseg = t & 3;
    const int brow = t >> 4, bseg = t & 15;

    float c[4][4] = {};

    for (int k0 = 0; k0 < 512; k0 += 16) {
        float4 av = *(const float4*)&x[(m0 + arow) * 512 + k0 + aseg * 4];
        As[(aseg * 4 + 0) * 68 + arow] = av.x;
        As[(aseg * 4 + 1) * 68 + arow] = av.y;
        As[(aseg * 4 + 2) * 68 + arow] = av.z;
        As[(aseg * 4 + 3) * 68 + arow] = av.w;
        *(float4*)&Bs[brow * 64 + bseg * 4] =
            *(const float4*)&W[(k0 + brow) * 1536 + n0 + bseg * 4];
        __syncthreads();
#pragma unroll
        for (int k = 0; k < 16; ++k) {
            float4 a  = *(float4*)&As[k * 68 + tyy * 4];
            float4 bq = *(float4*)&Bs[k * 64 + txx * 4];
            c[0][0] += a.x * bq.x; c[0][1] += a.x * bq.y; c[0][2] += a.x * bq.z; c[0][3] += a.x * bq.w;
            c[1][0] += a.y * bq.x; c[1][1] += a.y * bq.y; c[1][2] += a.y * bq.z; c[1][3] += a.y * bq.w;
            c[2][0] += a.z * bq.x; c[2][1] += a.z * bq.y; c[2][2] += a.z * bq.z; c[2][3] += a.z * bq.w;
            c[3][0] += a.w * bq.x; c[3][1] += a.w * bq.y; c[3][2] += a.w * bq.z; c[3][3] += a.w * bq.w;
        }
        __syncthreads();
    }

    const int part = n0 >> 9;             // 0:q 1:k 2:v
    const int h    = (n0 >> 6) & 7;
    float* dst = (part == 0) ? g_q : ((part == 1) ? g_k : g_v);
#pragma unroll
    for (int i = 0; i < 4; ++i) {
        int m  = m0 + tyy * 4 + i;
        int tt = m >> 3, b = m & 7;
        float* drow = dst + ((size_t)((b * 8 + h) * 512 + tt)) * 64 + txx * 4;
        drow[0] = c[i][0]; drow[1] = c[i][1]; drow[2] = c[i][2]; drow[3] = c[i][3];
    }
}

// ============================================================================
// Kernel 2: rpe table.  rpe[r, dout] = sinusoidal(r-511) @ W_pos
// Block = 512 threads (one per dout), handles 16 r rows.
// ============================================================================
__global__ void rpe_kernel(const float* __restrict__ Wpos) {
    __shared__ float feat[16 * 512];   // 32KB
    const int r0 = blockIdx.x * 16;
    const int t  = threadIdx.x;        // 512 threads

#pragma unroll
    for (int rep = 0; rep < 16; ++rep) {
        int idx = rep * 512 + t;
        int rr  = idx >> 9;
        int c   = idx & 511;
        float rel  = (float)(r0 + rr - 511);
        int   cc   = c & 255;
        float freq = expf(-9.210340371976184f * (float)cc * (1.0f / 256.0f));
        float ang  = rel * freq;
        feat[idx]  = (c < 256) ? sinf(ang) : cosf(ang);
    }
    __syncthreads();

    float acc[16];
#pragma unroll
    for (int rr = 0; rr < 16; ++rr) acc[rr] = 0.f;

    for (int c = 0; c < 512; ++c) {
        float w = Wpos[c * 512 + t];
#pragma unroll
        for (int rr = 0; rr < 16; ++rr) acc[rr] += feat[rr * 512 + c] * w;
    }
#pragma unroll
    for (int rr = 0; rr < 16; ++rr) {
        int r = r0 + rr;
        if (r < RR) g_rpe[r * 512 + t] = acc[rr];
    }
}

// ============================================================================
// Kernel 3a: uk[b,h,j] = pos_u[h,:] . k[b,h,j,:]
// ============================================================================
__global__ void uk_kernel(const float* __restrict__ pos_u) {
    int id = blockIdx.x * 256 + threadIdx.x;   // < BHN*TT = 32768
    int h  = (id >> 9) & 7;
    const float4* kp = (const float4*)(g_k + (size_t)id * 64);
    const float4* up = (const float4*)(pos_u + h * 64);
    float acc = 0.f;
#pragma unroll
    for (int s = 0; s < 16; ++s) {
        float4 kk = kp[s], uu = up[s];
        acc += kk.x * uu.x + kk.y * uu.y + kk.z * uu.z + kk.w * uu.w;
    }
    g_uk[id] = acc;
}

// Kernel 3b: vr[r,h] = pos_v[h,:] . rpe[r,h,:]
__global__ void vr_kernel(const float* __restrict__ pos_v) {
    int id = blockIdx.x * 256 + threadIdx.x;
    if (id >= RR * HH) return;
    int r = id >> 3, h = id & 7;
    const float4* rp = (const float4*)(g_rpe + r * 512 + h * 64);
    const float4* vp = (const float4*)(pos_v + h * 64);
    float acc = 0.f;
#pragma unroll
    for (int s = 0; s < 16; ++s) {
        float4 rr = rp[s], vv = vp[s];
        acc += rr.x * vv.x + rr.y * vv.y + rr.z * vv.z + rr.w * vv.w;
    }
    g_vr[id] = acc;
}

// ============================================================================
// Kernel 4: fused attention.
// Block = 256 threads, handles TI=32 query rows for one (b,h).
// Phases: BD (banded rpe GEMM with scatter) -> AC -> softmax -> PV.
// ============================================================================
#define TI  32
#define ES  513     // e_s row stride (padded: conflict-free finalize)
#define TLD 65      // tile row stride

__global__ void attn_kernel(const float* __restrict__ tau_ptr) {
    extern __shared__ float sm[];
    float* q_s  = sm;                   // [d][ii]   64*32
    float* e_s  = q_s + 64 * TI;        // [ii][j]   32*513
    float* tile = e_s + TI * ES;        // [row][d]  64*65 (rpe / K / V staging)
    float* red  = tile + 64 * TLD;      // [32][8]
    float* rowm = red + 256;            // [32]
    float* rowl = rowm + 32;            // [32]

    const int bh = blockIdx.y;
    const int h  = bh & 7;
    const int b  = bh >> 3;
    const int i0 = blockIdx.x * TI;
    const int tid = threadIdx.x;
    const int ty = tid >> 5, tx = tid & 31;

    // load Q tile transposed: q_s[d*TI + ii]
    const float* qg = g_q + ((size_t)bh * TT + i0) * 64;
    for (int idx = tid; idx < TI * 64; idx += 256) {
        int ii = idx >> 6, d = idx & 63;
        q_s[d * TI + ii] = qg[idx];
    }
    for (int idx = tid; idx < TI * ES; idx += 256) e_s[idx] = 0.f;
    __syncthreads();

    // ---------------- Phase A: BD term (q . rpe[i-j]) ----------------
    for (int ch = 0; ch < 9; ++ch) {
        __syncthreads();
        int rbase = i0 + ch * 64;
#pragma unroll
        for (int rep = 0; rep < 4; ++rep) {
            int f = rep * 256 + tid;         // 0..1023 float4 slots
            int row = f >> 4, seg = f & 15;
            int r = rbase + row;
            float4 vv = make_float4(0.f, 0.f, 0.f, 0.f);
            if (r < RR) vv = *(const float4*)&g_rpe[(size_t)r * 512 + h * 64 + seg * 4];
            float* dstp = &tile[row * TLD + seg * 4];
            dstp[0] = vv.x; dstp[1] = vv.y; dstp[2] = vv.z; dstp[3] = vv.w;
        }
        __syncthreads();

        int u0 = ch * 64 + tx;
        int u1 = u0 + 32;
        float a[4][2] = {};
        const float* t0 = &tile[tx * TLD];
        const float* t1 = &tile[(tx + 32) * TLD];
#pragma unroll
        for (int d = 0; d < 64; ++d) {
            float4 qv = *(float4*)&q_s[d * TI + ty * 4];
            float r0v = t0[d], r1v = t1[d];
            a[0][0] += qv.x * r0v; a[0][1] += qv.x * r1v;
            a[1][0] += qv.y * r0v; a[1][1] += qv.y * r1v;
            a[2][0] += qv.z * r0v; a[2][1] += qv.z * r1v;
            a[3][0] += qv.w * r0v; a[3][1] += qv.w * r1v;
        }
#pragma unroll
        for (int r = 0; r < 4; ++r) {
            int ii = ty * 4 + r;
            int j0 = ii - u0 + 511;
            int j1 = ii - u1 + 511;
            if (j0 >= 0 && j0 < 512) e_s[ii * ES + j0] += a[r][0];
            if (j1 >= 0 && j1 < 512) e_s[ii * ES + j1] += a[r][1];
        }
    }

    // ---------------- Phase B: AC term (q . k) ----------------
    for (int jc = 0; jc < 8; ++jc) {
        __syncthreads();
        const float4* ksrc = (const float4*)(g_k + ((size_t)bh * TT + jc * 64) * 64);
#pragma unroll
        for (int rep = 0; rep < 4; ++rep) {
            int f = rep * 256 + tid;
            int row = f >> 4, seg = f & 15;
            float4 vv = ksrc[f];
            float* dstp = &tile[row * TLD + seg * 4];
            dstp[0] = vv.x; dstp[1] = vv.y; dstp[2] = vv.z; dstp[3] = vv.w;
        }
        __syncthreads();

        float a[4][2] = {};
        const float* t0 = &tile[tx * TLD];
        const float* t1 = &tile[(tx + 32) * TLD];
#pragma unroll
        for (int d = 0; d < 64; ++d) {
            float4 qv = *(float4*)&q_s[d * TI + ty * 4];
            float k0v = t0[d], k1v = t1[d];
            a[0][0] += qv.x * k0v; a[0][1] += qv.x * k1v;
            a[1][0] += qv.y * k0v; a[1][1] += qv.y * k1v;
            a[2][0] += qv.z * k0v; a[2][1] += qv.z * k1v;
            a[3][0] += qv.w * k0v; a[3][1] += qv.w * k1v;
        }
        int jb = jc * 64 + tx;
#pragma unroll
        for (int r = 0; r < 4; ++r) {
            int ii = ty * 4 + r;
            e_s[ii * ES + jb]      += a[r][0];
            e_s[ii * ES + jb + 32] += a[r][1];
        }
    }
    __syncthreads();

    // ---------------- finalize: bias terms, scale, mask, softmax ----------------
    const float scale = 0.125f;                 // DH^-0.5
    const float tauf  = expf(tau_ptr[0]);
    {
        int row = tid & 31, seg = tid >> 5;     // row-major threads: conflict-free
        int ig  = i0 + row;
        const float* ukp = g_uk + bh * TT;
        float mloc = -FLT_MAX;
        for (int c = 0; c < 64; ++c) {
            int j = seg * 64 + c;
            float val = e_s[row * ES + j];
            val += ukp[j] + g_vr[(ig - j + 511) * 8 + h];
            val *= scale;
            if (j == ig) val = -FLT_MAX;        // diagonal mask (before tau, as in ref)
            val *= tauf;
            e_s[row * ES + j] = val;
            mloc = fmaxf(mloc, val);
        }
        red[row * 8 + seg] = mloc;
        __syncthreads();
        if (tid < 32) {
            float m = red[tid * 8];
#pragma unroll
            for (int s = 1; s < 8; ++s) m = fmaxf(m, red[tid * 8 + s]);
            rowm[tid] = m;
        }
        __syncthreads();
        float m = rowm[row];
        float sloc = 0.f;
        for (int c = 0; c < 64; ++c) {
            int j = seg * 64 + c;
            float p = __expf(e_s[row * ES + j] - m);
            e_s[row * ES + j] = p;
            sloc += p;
        }
        red[row * 8 + seg] = sloc;
        __syncthreads();
        if (tid < 32) {
            float s = 0.f;
#pragma unroll
            for (int ss = 0; ss < 8; ++ss) s += red[tid * 8 + ss];
            rowl[tid] = s;
        }
        __syncthreads();
    }

    // ---------------- Phase C: O = P @ V ----------------
    float o[4][2] = {};
    for (int jc = 0; jc < 8; ++jc) {
        __syncthreads();
        const float4* vsrc = (const float4*)(g_v + ((size_t)bh * TT + jc * 64) * 64);
#pragma unroll
        for (int rep = 0; rep < 4; ++rep) {
            int f = rep * 256 + tid;
            int row = f >> 4, seg = f & 15;
            float4 vv = vsrc[f];
            float* dstp = &tile[row * TLD + seg * 4];
            dstp[0] = vv.x; dstp[1] = vv.y; dstp[2] = vv.z; dstp[3] = vv.w;
        }
        __syncthreads();
#pragma unroll 8
        for (int jj = 0; jj < 64; ++jj) {
            int j = jc * 64 + jj;
            float v0 = tile[jj * TLD + tx];
            float v1 = tile[jj * TLD + tx + 32];
#pragma unroll
            for (int r = 0; r < 4; ++r) {
                float p = e_s[(ty * 4 + r) * ES + j];
                o[r][0] += p * v0;
                o[r][1] += p * v1;
            }
        }
    }
    __syncthreads();

#pragma unroll
    for (int r = 0; r < 4; ++r) {
        int ii = ty * 4 + r;
        int ig = i0 + ii;
        float inv = 1.f / rowl[ii];
        float* op = g_ao + (size_t)ig * (BB * DD) + b * DD + h * 64;
        op[tx]      = o[r][0] * inv;
        op[tx + 32] = o[r][1] * inv;
    }
}

// ============================================================================
// Kernel 5: output projection.  out(4096,512) = g_ao @ W_out + b_out
// ============================================================================
__global__ void out_gemm_kernel(const float* __restrict__ W,
                                const float* __restrict__ bias,
                                float* __restrict__ out) {
    __shared__ float As[16 * 68];
    __shared__ float Bs[16 * 64];
    const int m0 = blockIdx.y * 64;
    const int n0 = blockIdx.x * 64;
    const int t  = threadIdx.x;
    const int tyy = t >> 4, txx = t & 15;
    const int arow = t >> 2, aseg = t & 3;
    const int brow = t >> 4, bseg = t & 15;

    float c[4][4] = {};

    for (int k0 = 0; k0 < 512; k0 += 16) {
        float4 av = *(const float4*)&g_ao[(size_t)(m0 + arow) * 512 + k0 + aseg * 4];
        As[(aseg * 4 + 0) * 68 + arow] = av.x;
        As[(aseg * 4 + 1) * 68 + arow] = av.y;
        As[(aseg * 4 + 2) * 68 + arow] = av.z;
        As[(aseg * 4 + 3) * 68 + arow] = av.w;
        *(float4*)&Bs[brow * 64 + bseg * 4] =
            *(const float4*)&W[(k0 + brow) * 512 + n0 + bseg * 4];
        __syncthreads();
#pragma unroll
        for (int k = 0; k < 16; ++k) {
            float4 a  = *(float4*)&As[k * 68 + tyy * 4];
            float4 bq = *(float4*)&Bs[k * 64 + txx * 4];
            c[0][0] += a.x * bq.x; c[0][1] += a.x * bq.y; c[0][2] += a.x * bq.z; c[0][3] += a.x * bq.w;
            c[1][0] += a.y * bq.x; c[1][1] += a.y * bq.y; c[1][2] += a.y * bq.z; c[1][3] += a.y * bq.w;
            c[2][0] += a.z * bq.x; c[2][1] += a.z * bq.y; c[2][2] += a.z * bq.z; c[2][3] += a.z * bq.w;
            c[3][0] += a.w * bq.x; c[3][1] += a.w * bq.y; c[3][2] += a.w * bq.z; c[3][3] += a.w * bq.w;
        }
        __syncthreads();
    }

#pragma unroll
    for (int i = 0; i < 4; ++i) {
        int m = m0 + tyy * 4 + i;
#pragma unroll
        for (int j = 0; j < 4; ++j) {
            int n = n0 + txx * 4 + j;
            out[(size_t)m * 512 + n] = c[i][j] + bias[n];
        }
    }
}

// ============================================================================
extern "C" void kernel_launch(void* const* d_in, const int* in_sizes, int n_in,
                              void* d_out, int out_size) {
    const float* x     = (const float*)d_in[0];
    const float* Wqkv  = (const float*)d_in[1];
    const float* Wpos  = (const float*)d_in[2];
    const float* pos_u = (const float*)d_in[3];
    const float* pos_v = (const float*)d_in[4];
    const float* Wout  = (const float*)d_in[5];
    const float* bout  = (const float*)d_in[6];
    const float* ltau  = (const float*)d_in[7];
    float* out = (float*)d_out;

    qkv_gemm_kernel<<<dim3(24, 64), 256>>>(x, Wqkv);
    rpe_kernel<<<64, 512>>>(Wpos);
    uk_kernel<<<128, 256>>>(pos_u);
    vr_kernel<<<32, 256>>>(pos_v);

    const size_t smem = (size_t)(64 * TI + TI * ES + 64 * TLD + 256 + 32 + 32) * sizeof(float);
    cudaFuncSetAttribute(attn_kernel, cudaFuncAttributeMaxDynamicSharedMemorySize, (int)smem);
    attn_kernel<<<dim3(16, 64), 256, smem>>>(ltau);

    out_gemm_kernel<<<dim3(8, 64), 256>>>(Wout, bout, out);
}

// round 2
// speedup vs baseline: 1.7591x; 1.7591x over previous
#include <cuda_runtime.h>
#include <math.h>
#include <float.h>
#include <stdint.h>

// Problem constants
#define TT   512
#define BB   8
#define DD   512
#define HH   8
#define DHH  64
#define RR   1023
#define BHN  64
#define MROWS 4096

// ---------------- scratch ----------------
__device__ float g_q[BHN * TT * DHH];      // [b*8+h][t][dh]
__device__ float g_k[BHN * TT * DHH];
__device__ float g_v[BHN * TT * DHH];
__device__ float g_rpe[RR * DD];           // [r][h*64+dh]
__device__ float g_uk[BHN * TT];
__device__ float g_vr[RR * HH];
__device__ float g_ao[MROWS * DD];         // (t,b,d)

// ---------------- tf32 mma helpers ----------------
__device__ __forceinline__ uint32_t f2tf(float f) {
    uint32_t u;
    asm("cvt.rna.tf32.f32 %0, %1;" : "=r"(u) : "f"(f));
    return u;
}

__device__ __forceinline__ void mma8(float* c, const uint32_t* a, const uint32_t* b) {
    asm volatile(
        "mma.sync.aligned.m16n8k8.row.col.f32.tf32.tf32.f32 "
        "{%0,%1,%2,%3},{%4,%5,%6,%7},{%8,%9},{%0,%1,%2,%3};"
        : "+f"(c[0]), "+f"(c[1]), "+f"(c[2]), "+f"(c[3])
        : "r"(a[0]), "r"(a[1]), "r"(a[2]), "r"(a[3]), "r"(b[0]), "r"(b[1]));
}

// ============================================================================
// QKV GEMM (tf32 mma): C(4096,1536) = x(4096,512) @ W(512,1536)
// block tile 128x64, BK=32, 256 threads (8 warps, 4x2), warp tile 32x32
// ============================================================================
__global__ void qkv_mma_kernel(const float* __restrict__ x,
                               const float* __restrict__ W) {
    __shared__ uint32_t As[128 * 36];   // [m][k] pad->conflict-free frags
    __shared__ uint32_t Bs[32 * 68];    // [k][n]
    const int m0 = blockIdx.y * 128, n0 = blockIdx.x * 64;
    const int tid = threadIdx.x, lane = tid & 31, wid = tid >> 5;
    const int gi = lane >> 2, ti = lane & 3;
    const int wm = wid >> 1, wn = wid & 1;

    float c[2][4][4] = {};

    for (int k0 = 0; k0 < 512; k0 += 32) {
#pragma unroll
        for (int rep = 0; rep < 4; ++rep) {
            int s = rep * 256 + tid;            // 1024 float4 slots (A)
            int row = s >> 3, kseg = s & 7;
            float4 v = *(const float4*)&x[(size_t)(m0 + row) * 512 + k0 + kseg * 4];
            uint32_t* d = &As[row * 36 + kseg * 4];
            d[0] = f2tf(v.x); d[1] = f2tf(v.y); d[2] = f2tf(v.z); d[3] = f2tf(v.w);
        }
#pragma unroll
        for (int rep = 0; rep < 2; ++rep) {
            int s = rep * 256 + tid;            // 512 float4 slots (B)
            int row = s >> 4, nseg = s & 15;
            float4 v = *(const float4*)&W[(size_t)(k0 + row) * 1536 + n0 + nseg * 4];
            uint32_t* d = &Bs[row * 68 + nseg * 4];
            d[0] = f2tf(v.x); d[1] = f2tf(v.y); d[2] = f2tf(v.z); d[3] = f2tf(v.w);
        }
        __syncthreads();
#pragma unroll
        for (int kb = 0; kb < 32; kb += 8) {
            uint32_t a[2][4];
#pragma unroll
            for (int mt = 0; mt < 2; ++mt) {
                int r = wm * 32 + mt * 16 + gi;
                a[mt][0] = As[r * 36 + kb + ti];
                a[mt][1] = As[(r + 8) * 36 + kb + ti];
                a[mt][2] = As[r * 36 + kb + ti + 4];
                a[mt][3] = As[(r + 8) * 36 + kb + ti + 4];
            }
#pragma unroll
            for (int nt = 0; nt < 4; ++nt) {
                uint32_t bf[2];
                int ncol = wn * 32 + nt * 8 + gi;
                bf[0] = Bs[(kb + ti) * 68 + ncol];
                bf[1] = Bs[(kb + ti + 4) * 68 + ncol];
                mma8(c[0][nt], a[0], bf);
                mma8(c[1][nt], a[1], bf);
            }
        }
        __syncthreads();
    }

    // scatter epilogue into g_q/g_k/g_v  [b*8+h][t][dh]
#pragma unroll
    for (int mt = 0; mt < 2; ++mt) {
        int m = m0 + wm * 32 + mt * 16 + gi;
#pragma unroll
        for (int nt = 0; nt < 4; ++nt) {
            int n = n0 + wn * 32 + nt * 8 + 2 * ti;
            int part = n >> 9;
            int hh = (n >> 6) & 7;
            int dh = n & 63;
            float* dst = (part == 0) ? g_q : ((part == 1) ? g_k : g_v);
            int tr = m >> 3, bi = m & 7;
            size_t off = ((size_t)((bi * 8 + hh) * 512 + tr)) * 64 + dh;
            *(float2*)&dst[off] = make_float2(c[mt][nt][0], c[mt][nt][1]);
            int m2 = m + 8;
            int tr2 = m2 >> 3, bi2 = m2 & 7;
            size_t off2 = ((size_t)((bi2 * 8 + hh) * 512 + tr2)) * 64 + dh;
            *(float2*)&dst[off2] = make_float2(c[mt][nt][2], c[mt][nt][3]);
        }
    }
}

// ============================================================================
// rpe GEMM (tf32 mma): g_rpe(1023,512) = sinusoid(1024,512) @ W_pos(512,512)
// A generated on the fly. block 128x64, BK=32, 256 threads.
// ============================================================================
__global__ void rpe_mma_kernel(const float* __restrict__ Wpos) {
    __shared__ uint32_t As[128 * 36];
    __shared__ uint32_t Bs[32 * 68];
    __shared__ float freqs[512];
    const int m0 = blockIdx.y * 128, n0 = blockIdx.x * 64;
    const int tid = threadIdx.x, lane = tid & 31, wid = tid >> 5;
    const int gi = lane >> 2, ti = lane & 3;
    const int wm = wid >> 1, wn = wid & 1;

    for (int s = tid; s < 512; s += 256) {
        int cc = s & 255;
        freqs[s] = __expf(-9.210340371976184f * (float)cc * (1.0f / 256.0f));
    }
    __syncthreads();

    float c[2][4][4] = {};

    for (int k0 = 0; k0 < 512; k0 += 32) {
#pragma unroll
        for (int rep = 0; rep < 16; ++rep) {
            int s = rep * 256 + tid;            // 4096 scalar slots (A gen)
            int row = s >> 5, kk = s & 31;
            int cgl = k0 + kk;
            float rel = (float)(m0 + row - 511);
            float ang = rel * freqs[cgl];
            float v = (cgl < 256) ? sinf(ang) : cosf(ang);
            As[row * 36 + kk] = f2tf(v);
        }
#pragma unroll
        for (int rep = 0; rep < 2; ++rep) {
            int s = rep * 256 + tid;
            int row = s >> 4, nseg = s & 15;
            float4 v = *(const float4*)&Wpos[(size_t)(k0 + row) * 512 + n0 + nseg * 4];
            uint32_t* d = &Bs[row * 68 + nseg * 4];
            d[0] = f2tf(v.x); d[1] = f2tf(v.y); d[2] = f2tf(v.z); d[3] = f2tf(v.w);
        }
        __syncthreads();
#pragma unroll
        for (int kb = 0; kb < 32; kb += 8) {
            uint32_t a[2][4];
#pragma unroll
            for (int mt = 0; mt < 2; ++mt) {
                int r = wm * 32 + mt * 16 + gi;
                a[mt][0] = As[r * 36 + kb + ti];
                a[mt][1] = As[(r + 8) * 36 + kb + ti];
                a[mt][2] = As[r * 36 + kb + ti + 4];
                a[mt][3] = As[(r + 8) * 36 + kb + ti + 4];
            }
#pragma unroll
            for (int nt = 0; nt < 4; ++nt) {
                uint32_t bf[2];
                int ncol = wn * 32 + nt * 8 + gi;
                bf[0] = Bs[(kb + ti) * 68 + ncol];
                bf[1] = Bs[(kb + ti + 4) * 68 + ncol];
                mma8(c[0][nt], a[0], bf);
                mma8(c[1][nt], a[1], bf);
            }
        }
        __syncthreads();
    }

#pragma unroll
    for (int mt = 0; mt < 2; ++mt) {
        int m = m0 + wm * 32 + mt * 16 + gi;
#pragma unroll
        for (int nt = 0; nt < 4; ++nt) {
            int n = n0 + wn * 32 + nt * 8 + 2 * ti;
            if (m < RR)
                *(float2*)&g_rpe[(size_t)m * 512 + n] = make_float2(c[mt][nt][0], c[mt][nt][1]);
            if (m + 8 < RR)
                *(float2*)&g_rpe[(size_t)(m + 8) * 512 + n] = make_float2(c[mt][nt][2], c[mt][nt][3]);
        }
    }
}

// ============================================================================
// small bias kernels (unchanged)
// ============================================================================
__global__ void uk_kernel(const float* __restrict__ pos_u) {
    int id = blockIdx.x * 256 + threadIdx.x;
    int h = (id >> 9) & 7;
    const float4* kp = (const float4*)(g_k + (size_t)id * 64);
    const float4* up = (const float4*)(pos_u + h * 64);
    float acc = 0.f;
#pragma unroll
    for (int s = 0; s < 16; ++s) {
        float4 kk = kp[s], uu = up[s];
        acc += kk.x * uu.x + kk.y * uu.y + kk.z * uu.z + kk.w * uu.w;
    }
    g_uk[id] = acc;
}

__global__ void vr_kernel(const float* __restrict__ pos_v) {
    int id = blockIdx.x * 256 + threadIdx.x;
    if (id >= RR * HH) return;
    int r = id >> 3, h = id & 7;
    const float4* rp = (const float4*)(g_rpe + r * 512 + h * 64);
    const float4* vp = (const float4*)(pos_v + h * 64);
    float acc = 0.f;
#pragma unroll
    for (int s = 0; s < 16; ++s) {
        float4 rr = rp[s], vv = vp[s];
        acc += rr.x * vv.x + rr.y * vv.y + rr.z * vv.z + rr.w * vv.w;
    }
    g_vr[id] = acc;
}

// ============================================================================
// Fused attention (tf32 mma).
// Block = 512 threads (16 warps, 4x4), TI=64 query rows per block, one (b,h).
// e_s stored TRANSPOSED: e_s[j][i], ld=68 -> AC/BD use K/rpe rows directly as
// A operands; Q transposed once as shared B operand; PV reads P from e_s as A.
// ============================================================================
#define LDE 68

__global__ void attn_mma_kernel(const float* __restrict__ tau_ptr) {
    extern __shared__ float sm[];
    float* e_s  = sm;                       // [512][68]
    float* Qsf  = e_s + 512 * LDE;          // Q^T tf32 bits [d=64][68]
    float* Tsf  = Qsf + 64 * LDE;           // staging [64][68]
    float* uks  = Tsf + 64 * LDE;           // 512
    float* vrs  = uks + 512;                // 576
    float* red  = vrs + 576;                // [8][64]
    float* rowm = red + 512;                // 64
    float* rowl = rowm + 64;                // 64
    uint32_t* Qs = (uint32_t*)Qsf;
    uint32_t* Ts = (uint32_t*)Tsf;

    const int bh = blockIdx.y, h = bh & 7, b = bh >> 3;
    const int i0 = blockIdx.x * 64;
    const int tid = threadIdx.x, lane = tid & 31, wid = tid >> 5;
    const int gi = lane >> 2, ti = lane & 3;
    const int wm = wid >> 2, wn = wid & 3;          // 4x4 warp grid
    const int mw = wm * 16, nw = wn * 16;

    // ---- init: Q^T, zero e_s, stage uk / vr slices ----
    {
        const float4* qg = (const float4*)(g_q + ((size_t)bh * TT + i0) * 64);
        for (int s = tid; s < 1024; s += 512) {
            int ii = s >> 4, dseg = s & 15;
            float4 v = qg[s];
            Qs[(dseg * 4 + 0) * LDE + ii] = f2tf(v.x);
            Qs[(dseg * 4 + 1) * LDE + ii] = f2tf(v.y);
            Qs[(dseg * 4 + 2) * LDE + ii] = f2tf(v.z);
            Qs[(dseg * 4 + 3) * LDE + ii] = f2tf(v.w);
        }
        for (int s = tid; s < 512 * LDE; s += 512) e_s[s] = 0.f;
        for (int s = tid; s < 512; s += 512) uks[s] = g_uk[bh * 512 + s];
        for (int s = tid; s < 576; s += 512) {
            int u = i0 + s;
            vrs[s] = (u < RR) ? g_vr[u * 8 + h] : 0.f;
        }
    }
    __syncthreads();

    // ---- Phase BD: bd^T[u', i'] = rpe[u] . q[i]; scatter j = i - u + 511 ----
    for (int ch = 0; ch < 9; ++ch) {
        int ub = i0 + ch * 64;
        for (int s = tid; s < 1024; s += 512) {
            int row = s >> 4, seg = s & 15;
            int u = ub + row;
            float4 v = make_float4(0.f, 0.f, 0.f, 0.f);
            if (u < RR) v = *(const float4*)&g_rpe[(size_t)u * 512 + h * 64 + seg * 4];
            uint32_t* d = &Ts[row * LDE + seg * 4];
            d[0] = f2tf(v.x); d[1] = f2tf(v.y); d[2] = f2tf(v.z); d[3] = f2tf(v.w);
        }
        __syncthreads();

        float c[2][4] = {};
#pragma unroll
        for (int kb = 0; kb < 64; kb += 8) {
            uint32_t a[4];
            a[0] = Ts[(mw + gi) * LDE + kb + ti];
            a[1] = Ts[(mw + gi + 8) * LDE + kb + ti];
            a[2] = Ts[(mw + gi) * LDE + kb + ti + 4];
            a[3] = Ts[(mw + gi + 8) * LDE + kb + ti + 4];
#pragma unroll
            for (int nn = 0; nn < 2; ++nn) {
                uint32_t bf[2];
                int ncol = nw + nn * 8 + gi;
                bf[0] = Qs[(kb + ti) * LDE + ncol];
                bf[1] = Qs[(kb + ti + 4) * LDE + ncol];
                mma8(c[nn], a, bf);
            }
        }
#pragma unroll
        for (int nn = 0; nn < 2; ++nn) {
            int ip = nw + nn * 8 + 2 * ti;
            int base = ip - ch * 64 + 511;
            int j0 = base - (mw + gi);
            int j2 = j0 - 8;
            if ((unsigned)j0 < 512u)       e_s[j0 * LDE + ip]       += c[nn][0];
            if ((unsigned)(j0 + 1) < 512u) e_s[(j0 + 1) * LDE + ip + 1] += c[nn][1];
            if ((unsigned)j2 < 512u)       e_s[j2 * LDE + ip]       += c[nn][2];
            if ((unsigned)(j2 + 1) < 512u) e_s[(j2 + 1) * LDE + ip + 1] += c[nn][3];
        }
        __syncthreads();
    }

    // ---- Phase AC: e^T[j', i'] += k[j] . q[i] ----
    for (int jc = 0; jc < 8; ++jc) {
        const float4* ksrc = (const float4*)(g_k + ((size_t)bh * TT + jc * 64) * 64);
        for (int s = tid; s < 1024; s += 512) {
            int row = s >> 4, seg = s & 15;
            float4 v = ksrc[s];
            uint32_t* d = &Ts[row * LDE + seg * 4];
            d[0] = f2tf(v.x); d[1] = f2tf(v.y); d[2] = f2tf(v.z); d[3] = f2tf(v.w);
        }
        __syncthreads();

        float c[2][4] = {};
#pragma unroll
        for (int kb = 0; kb < 64; kb += 8) {
            uint32_t a[4];
            a[0] = Ts[(mw + gi) * LDE + kb + ti];
            a[1] = Ts[(mw + gi + 8) * LDE + kb + ti];
            a[2] = Ts[(mw + gi) * LDE + kb + ti + 4];
            a[3] = Ts[(mw + gi + 8) * LDE + kb + ti + 4];
#pragma unroll
            for (int nn = 0; nn < 2; ++nn) {
                uint32_t bf[2];
                int ncol = nw + nn * 8 + gi;
                bf[0] = Qs[(kb + ti) * LDE + ncol];
                bf[1] = Qs[(kb + ti + 4) * LDE + ncol];
                mma8(c[nn], a, bf);
            }
        }
        int jg = jc * 64 + mw + gi;
#pragma unroll
        for (int nn = 0; nn < 2; ++nn) {
            int ip = nw + nn * 8 + 2 * ti;
            e_s[jg * LDE + ip]           += c[nn][0];
            e_s[jg * LDE + ip + 1]       += c[nn][1];
            e_s[(jg + 8) * LDE + ip]     += c[nn][2];
            e_s[(jg + 8) * LDE + ip + 1] += c[nn][3];
        }
        __syncthreads();
    }

    // ---- finalize + softmax over j (rows of e_s^T), per column i ----
    {
        const float scale = 0.125f;
        const float tauf = expf(tau_ptr[0]);
        int col = tid & 63, seg = tid >> 6;     // 8 segs x 64 j
        int ig = i0 + col;
        float mloc = -FLT_MAX;
        for (int jj = 0; jj < 64; ++jj) {
            int j = seg * 64 + jj;
            float val = e_s[j * LDE + col];
            val = (val + uks[j] + vrs[col - j + 511]) * scale;
            if (j == ig) val = -FLT_MAX;
            val *= tauf;
            e_s[j * LDE + col] = val;
            mloc = fmaxf(mloc, val);
        }
        red[seg * 64 + col] = mloc;
        __syncthreads();
        if (tid < 64) {
            float m = red[tid];
#pragma unroll
            for (int s = 1; s < 8; ++s) m = fmaxf(m, red[s * 64 + tid]);
            rowm[tid] = m;
        }
        __syncthreads();
        float m = rowm[col];
        float sloc = 0.f;
        for (int jj = 0; jj < 64; ++jj) {
            int j = seg * 64 + jj;
            float p = __expf(e_s[j * LDE + col] - m);
            e_s[j * LDE + col] = p;
            sloc += p;
        }
        red[seg * 64 + col] = sloc;
        __syncthreads();
        if (tid < 64) {
            float s = 0.f;
#pragma unroll
            for (int ss = 0; ss < 8; ++ss) s += red[ss * 64 + tid];
            rowl[tid] = s;
        }
        __syncthreads();
    }

    // ---- Phase PV: O[i, dh] = sum_j P[i,j] V[j,dh]; A=P from e_s, B=V staged ----
    float o[2][4] = {};
    const uint32_t* Pu = (const uint32_t*)e_s;
    for (int jc = 0; jc < 8; ++jc) {
        __syncthreads();
        const float4* vsrc = (const float4*)(g_v + ((size_t)bh * TT + jc * 64) * 64);
        for (int s = tid; s < 1024; s += 512) {
            int row = s >> 4, seg = s & 15;
            float4 v = vsrc[s];
            uint32_t* d = &Ts[row * LDE + seg * 4];
            d[0] = f2tf(v.x); d[1] = f2tf(v.y); d[2] = f2tf(v.z); d[3] = f2tf(v.w);
        }
        __syncthreads();
#pragma unroll
        for (int kb = 0; kb < 64; kb += 8) {
            int jr = jc * 64 + kb;
            uint32_t a[4];
            a[0] = Pu[(jr + ti) * LDE + mw + gi];
            a[1] = Pu[(jr + ti) * LDE + mw + gi + 8];
            a[2] = Pu[(jr + ti + 4) * LDE + mw + gi];
            a[3] = Pu[(jr + ti + 4) * LDE + mw + gi + 8];
            // NOTE: A fragment wants (m,k): a0=(g,t) a1=(g+8,t) a2=(g,t+4) a3=(g+8,t+4)
            // addresses above give value P[i=mw+gi(+8)][j=jr+ti(+4)] as required.
#pragma unroll
            for (int nn = 0; nn < 2; ++nn) {
                uint32_t bf[2];
                int ncol = nw + nn * 8 + gi;
                bf[0] = Ts[(kb + ti) * LDE + ncol];
                bf[1] = Ts[(kb + ti + 4) * LDE + ncol];
                mma8(o[nn], a, bf);
            }
        }
    }
    __syncthreads();

    {
        int i1 = mw + gi, i2 = mw + gi + 8;
        float inv1 = 1.f / rowl[i1];
        float inv2 = 1.f / rowl[i2];
#pragma unroll
        for (int nn = 0; nn < 2; ++nn) {
            int dh = nw + nn * 8 + 2 * ti;
            float* o1 = g_ao + (size_t)(i0 + i1) * (BB * DD) + b * DD + h * 64 + dh;
            float* o2 = g_ao + (size_t)(i0 + i2) * (BB * DD) + b * DD + h * 64 + dh;
            *(float2*)o1 = make_float2(o[nn][0] * inv1, o[nn][1] * inv1);
            *(float2*)o2 = make_float2(o[nn][2] * inv2, o[nn][3] * inv2);
        }
    }
}

// ============================================================================
// Output projection (tf32 mma): out(4096,512) = g_ao @ W_out + b_out
// ============================================================================
__global__ void out_mma_kernel(const float* __restrict__ W,
                               const float* __restrict__ bias,
                               float* __restrict__ out) {
    __shared__ uint32_t As[128 * 36];
    __shared__ uint32_t Bs[32 * 68];
    const int m0 = blockIdx.y * 128, n0 = blockIdx.x * 64;
    const int tid = threadIdx.x, lane = tid & 31, wid = tid >> 5;
    const int gi = lane >> 2, ti = lane & 3;
    const int wm = wid >> 1, wn = wid & 1;

    float c[2][4][4] = {};

    for (int k0 = 0; k0 < 512; k0 += 32) {
#pragma unroll
        for (int rep = 0; rep < 4; ++rep) {
            int s = rep * 256 + tid;
            int row = s >> 3, kseg = s & 7;
            float4 v = *(const float4*)&g_ao[(size_t)(m0 + row) * 512 + k0 + kseg * 4];
            uint32_t* d = &As[row * 36 + kseg * 4];
            d[0] = f2tf(v.x); d[1] = f2tf(v.y); d[2] = f2tf(v.z); d[3] = f2tf(v.w);
        }
#pragma unroll
        for (int rep = 0; rep < 2; ++rep) {
            int s = rep * 256 + tid;
            int row = s >> 4, nseg = s & 15;
            float4 v = *(const float4*)&W[(size_t)(k0 + row) * 512 + n0 + nseg * 4];
            uint32_t* d = &Bs[row * 68 + nseg * 4];
            d[0] = f2tf(v.x); d[1] = f2tf(v.y); d[2] = f2tf(v.z); d[3] = f2tf(v.w);
        }
        __syncthreads();
#pragma unroll
        for (int kb = 0; kb < 32; kb += 8) {
            uint32_t a[2][4];
#pragma unroll
            for (int mt = 0; mt < 2; ++mt) {
                int r = wm * 32 + mt * 16 + gi;
                a[mt][0] = As[r * 36 + kb + ti];
                a[mt][1] = As[(r + 8) * 36 + kb + ti];
                a[mt][2] = As[r * 36 + kb + ti + 4];
                a[mt][3] = As[(r + 8) * 36 + kb + ti + 4];
            }
#pragma unroll
            for (int nt = 0; nt < 4; ++nt) {
                uint32_t bf[2];
                int ncol = wn * 32 + nt * 8 + gi;
                bf[0] = Bs[(kb + ti) * 68 + ncol];
                bf[1] = Bs[(kb + ti + 4) * 68 + ncol];
                mma8(c[0][nt], a[0], bf);
                mma8(c[1][nt], a[1], bf);
            }
        }
        __syncthreads();
    }

#pragma unroll
    for (int mt = 0; mt < 2; ++mt) {
        int m = m0 + wm * 32 + mt * 16 + gi;
#pragma unroll
        for (int nt = 0; nt < 4; ++nt) {
            int n = n0 + wn * 32 + nt * 8 + 2 * ti;
            float b0 = bias[n], b1 = bias[n + 1];
            *(float2*)&out[(size_t)m * 512 + n] =
                make_float2(c[mt][nt][0] + b0, c[mt][nt][1] + b1);
            *(float2*)&out[(size_t)(m + 8) * 512 + n] =
                make_float2(c[mt][nt][2] + b0, c[mt][nt][3] + b1);
        }
    }
}

// ============================================================================
extern "C" void kernel_launch(void* const* d_in, const int* in_sizes, int n_in,
                              void* d_out, int out_size) {
    const float* x     = (const float*)d_in[0];
    const float* Wqkv  = (const float*)d_in[1];
    const float* Wpos  = (const float*)d_in[2];
    const float* pos_u = (const float*)d_in[3];
    const float* pos_v = (const float*)d_in[4];
    const float* Wout  = (const float*)d_in[5];
    const float* bout  = (const float*)d_in[6];
    const float* ltau  = (const float*)d_in[7];
    float* out = (float*)d_out;

    qkv_mma_kernel<<<dim3(24, 32), 256>>>(x, Wqkv);
    rpe_mma_kernel<<<dim3(8, 8), 256>>>(Wpos);
    uk_kernel<<<128, 256>>>(pos_u);
    vr_kernel<<<32, 256>>>(pos_v);

    const size_t smem = (size_t)(512 * LDE + 64 * LDE + 64 * LDE + 512 + 576 + 512 + 64 + 64) * sizeof(float);
    cudaFuncSetAttribute(attn_mma_kernel, cudaFuncAttributeMaxDynamicSharedMemorySize, (int)smem);
    attn_mma_kernel<<<dim3(8, 64), 512, smem>>>(ltau);

    out_mma_kernel<<<dim3(8, 32), 256>>>(Wout, bout, out);
}

// round 4
// speedup vs baseline: 2.0434x; 1.1616x over previous
#include <cuda_runtime.h>
#include <math.h>
#include <float.h>
#include <stdint.h>

#define TT   512
#define BB   8
#define DD   512
#define HH   8
#define DHH  64
#define RR   1023
#define BHN  64
#define MROWS 4096

// ---------------- scratch (tf32-bit payloads where noted) ----------------
__device__ float g_q[BHN * TT * DHH];      // tf32 bits  [b*8+h][t][dh]
__device__ float g_k[BHN * TT * DHH];      // tf32 bits
__device__ float g_v[BHN * TT * DHH];      // tf32 bits
__device__ float g_rpe[RR * DD];           // tf32 bits  [r][h*64+dh]
__device__ float g_uk[BHN * TT];
__device__ float g_vr[RR * HH];
__device__ float g_ao[MROWS * DD];         // fp32 (t,b,d)

__device__ __forceinline__ uint32_t f2tf(float f) {
    uint32_t u;
    asm("cvt.rna.tf32.f32 %0, %1;" : "=r"(u) : "f"(f));
    return u;
}

__device__ __forceinline__ void mma8(float* c, const uint32_t* a, const uint32_t* b) {
    asm volatile(
        "mma.sync.aligned.m16n8k8.row.col.f32.tf32.tf32.f32 "
        "{%0,%1,%2,%3},{%4,%5,%6,%7},{%8,%9},{%0,%1,%2,%3};"
        : "+f"(c[0]), "+f"(c[1]), "+f"(c[2]), "+f"(c[3])
        : "r"(a[0]), "r"(a[1]), "r"(a[2]), "r"(a[3]), "r"(b[0]), "r"(b[1]));
}

// ============================================================================
// QKV GEMM: C(4096,1536) = x @ W.  128x128 tile, BK=32, 256 thr, warp 64x32.
// Epilogue converts to tf32 bits and scatters to g_q/g_k/g_v [b,h,t,dh].
// ============================================================================
__global__ void __launch_bounds__(256, 2)
qkv_mma_kernel(const float* __restrict__ x, const float* __restrict__ W) {
    __shared__ uint32_t As[128 * 36];
    __shared__ uint32_t Bs[32 * 132];
    const int m0 = blockIdx.y * 128, n0 = blockIdx.x * 128;
    const int tid = threadIdx.x, lane = tid & 31, wid = tid >> 5;
    const int gi = lane >> 2, ti = lane & 3;
    const int wm = wid >> 2, wn = wid & 3;

    float c_[4][4][4] = {};

    for (int k0 = 0; k0 < 512; k0 += 32) {
#pragma unroll
        for (int rep = 0; rep < 4; ++rep) {
            int s = rep * 256 + tid;
            int row = s >> 3, kseg = s & 7;
            float4 v = *(const float4*)&x[(size_t)(m0 + row) * 512 + k0 + kseg * 4];
            uint32_t* d = &As[row * 36 + kseg * 4];
            d[0] = f2tf(v.x); d[1] = f2tf(v.y); d[2] = f2tf(v.z); d[3] = f2tf(v.w);
        }
#pragma unroll
        for (int rep = 0; rep < 4; ++rep) {
            int s = rep * 256 + tid;
            int row = s >> 5, nseg = s & 31;
            float4 v = *(const float4*)&W[(size_t)(k0 + row) * 1536 + n0 + nseg * 4];
            uint32_t* d = &Bs[row * 132 + nseg * 4];
            d[0] = f2tf(v.x); d[1] = f2tf(v.y); d[2] = f2tf(v.z); d[3] = f2tf(v.w);
        }
        __syncthreads();
#pragma unroll
        for (int kb = 0; kb < 32; kb += 8) {
            uint32_t a[4][4], bb[4][2];
#pragma unroll
            for (int mt = 0; mt < 4; ++mt) {
                int r = wm * 64 + mt * 16 + gi;
                a[mt][0] = As[r * 36 + kb + ti];
                a[mt][1] = As[(r + 8) * 36 + kb + ti];
                a[mt][2] = As[r * 36 + kb + ti + 4];
                a[mt][3] = As[(r + 8) * 36 + kb + ti + 4];
            }
#pragma unroll
            for (int nt = 0; nt < 4; ++nt) {
                int ncol = wn * 32 + nt * 8 + gi;
                bb[nt][0] = Bs[(kb + ti) * 132 + ncol];
                bb[nt][1] = Bs[(kb + ti + 4) * 132 + ncol];
            }
#pragma unroll
            for (int mt = 0; mt < 4; ++mt)
#pragma unroll
                for (int nt = 0; nt < 4; ++nt)
                    mma8(c_[mt][nt], a[mt], bb[nt]);
        }
        __syncthreads();
    }

#pragma unroll
    for (int mt = 0; mt < 4; ++mt) {
        int m = m0 + wm * 64 + mt * 16 + gi;
#pragma unroll
        for (int nt = 0; nt < 4; ++nt) {
            int n = n0 + wn * 32 + nt * 8 + 2 * ti;
            int part = n >> 9, hh = (n >> 6) & 7, dh = n & 63;
            float* dst = (part == 0) ? g_q : ((part == 1) ? g_k : g_v);
            int tr = m >> 3, bi = m & 7;
            size_t off = ((size_t)((bi * 8 + hh) * 512 + tr)) * 64 + dh;
            *(float2*)&dst[off] = make_float2(__uint_as_float(f2tf(c_[mt][nt][0])),
                                              __uint_as_float(f2tf(c_[mt][nt][1])));
            int m2 = m + 8;
            int tr2 = m2 >> 3, bi2 = m2 & 7;
            size_t off2 = ((size_t)((bi2 * 8 + hh) * 512 + tr2)) * 64 + dh;
            *(float2*)&dst[off2] = make_float2(__uint_as_float(f2tf(c_[mt][nt][2])),
                                               __uint_as_float(f2tf(c_[mt][nt][3])));
        }
    }
}

// ============================================================================
// rpe GEMM: g_rpe(1023,512) = sinusoid @ W_pos. 128x64, BK=32 (tf32 epilogue).
// ============================================================================
__global__ void __launch_bounds__(256)
rpe_mma_kernel(const float* __restrict__ Wpos) {
    __shared__ uint32_t As[128 * 36];
    __shared__ uint32_t Bs[32 * 68];
    __shared__ float freqs[512];
    const int m0 = blockIdx.y * 128, n0 = blockIdx.x * 64;
    const int tid = threadIdx.x, lane = tid & 31, wid = tid >> 5;
    const int gi = lane >> 2, ti = lane & 3;
    const int wm = wid >> 1, wn = wid & 1;

    for (int s = tid; s < 512; s += 256) {
        int cc = s & 255;
        freqs[s] = __expf(-9.210340371976184f * (float)cc * (1.0f / 256.0f));
    }
    __syncthreads();

    float c_[2][4][4] = {};

    for (int k0 = 0; k0 < 512; k0 += 32) {
#pragma unroll
        for (int rep = 0; rep < 16; ++rep) {
            int s = rep * 256 + tid;
            int row = s >> 5, kk = s & 31;
            int cgl = k0 + kk;
            float rel = (float)(m0 + row - 511);
            float ang = rel * freqs[cgl];
            float v = (cgl < 256) ? sinf(ang) : cosf(ang);
            As[row * 36 + kk] = f2tf(v);
        }
#pragma unroll
        for (int rep = 0; rep < 2; ++rep) {
            int s = rep * 256 + tid;
            int row = s >> 4, nseg = s & 15;
            float4 v = *(const float4*)&Wpos[(size_t)(k0 + row) * 512 + n0 + nseg * 4];
            uint32_t* d = &Bs[row * 68 + nseg * 4];
            d[0] = f2tf(v.x); d[1] = f2tf(v.y); d[2] = f2tf(v.z); d[3] = f2tf(v.w);
        }
        __syncthreads();
#pragma unroll
        for (int kb = 0; kb < 32; kb += 8) {
            uint32_t a[2][4];
#pragma unroll
            for (int mt = 0; mt < 2; ++mt) {
                int r = wm * 32 + mt * 16 + gi;
                a[mt][0] = As[r * 36 + kb + ti];
                a[mt][1] = As[(r + 8) * 36 + kb + ti];
                a[mt][2] = As[r * 36 + kb + ti + 4];
                a[mt][3] = As[(r + 8) * 36 + kb + ti + 4];
            }
#pragma unroll
            for (int nt = 0; nt < 4; ++nt) {
                uint32_t bf[2];
                int ncol = wn * 32 + nt * 8 + gi;
                bf[0] = Bs[(kb + ti) * 68 + ncol];
                bf[1] = Bs[(kb + ti + 4) * 68 + ncol];
                mma8(c_[0][nt], a[0], bf);
                mma8(c_[1][nt], a[1], bf);
            }
        }
        __syncthreads();
    }

#pragma unroll
    for (int mt = 0; mt < 2; ++mt) {
        int m = m0 + wm * 32 + mt * 16 + gi;
#pragma unroll
        for (int nt = 0; nt < 4; ++nt) {
            int n = n0 + wn * 32 + nt * 8 + 2 * ti;
            if (m < RR)
                *(float2*)&g_rpe[(size_t)m * 512 + n] =
                    make_float2(__uint_as_float(f2tf(c_[mt][nt][0])),
                                __uint_as_float(f2tf(c_[mt][nt][1])));
            if (m + 8 < RR)
                *(float2*)&g_rpe[(size_t)(m + 8) * 512 + n] =
                    make_float2(__uint_as_float(f2tf(c_[mt][nt][2])),
                                __uint_as_float(f2tf(c_[mt][nt][3])));
        }
    }
}

// ============================================================================
// bias kernels
// ============================================================================
__global__ void uk_kernel(const float* __restrict__ pos_u) {
    int id = blockIdx.x * 256 + threadIdx.x;
    int h = (id >> 9) & 7;
    const float4* kp = (const float4*)(g_k + (size_t)id * 64);
    const float4* up = (const float4*)(pos_u + h * 64);
    float acc = 0.f;
#pragma unroll
    for (int s = 0; s < 16; ++s) {
        float4 kk = kp[s], uu = up[s];
        acc += kk.x * uu.x + kk.y * uu.y + kk.z * uu.z + kk.w * uu.w;
    }
    g_uk[id] = acc;
}

__global__ void vr_kernel(const float* __restrict__ pos_v) {
    int id = blockIdx.x * 256 + threadIdx.x;
    if (id >= RR * HH) return;
    int r = id >> 3, h = id & 7;
    const float4* rp = (const float4*)(g_rpe + r * 512 + h * 64);
    const float4* vp = (const float4*)(pos_v + h * 64);
    float acc = 0.f;
#pragma unroll
    for (int s = 0; s < 16; ++s) {
        float4 rr = rp[s], vv = vp[s];
        acc += rr.x * vv.x + rr.y * vv.y + rr.z * vv.z + rr.w * vv.w;
    }
    g_vr[id] = acc;
}

// ============================================================================
// Fused attention. 512 threads, TI=64 i-rows per block, one (b,h).
// K/rpe staged in A-fragment layout (LDS.128), Q in B-fragment layout (LDS.64),
// V in B-fragment layout for PV. 256-row chunks, warp tiles 32x32 (AC/BD).
// ============================================================================
#define LDE 68

// stage 256 source rows (stride words apart, 64 cols) into A-frag layout
__device__ __forceinline__ void stage_A(uint32_t* Tf, const uint32_t* src,
                                        int stride, int maxrow, int tilecap,
                                        int wid, int lane) {
#pragma unroll
    for (int k = 0; k < 8; ++k) {
        int c = wid + (k << 4);          // c = mt*8 + ks
        int mt = c >> 3, ks = c & 7;
        if (mt >= tilecap) continue;
#pragma unroll
        for (int r = 0; r < 4; ++r) {
            int aidx = ((lane >> 3) + r) & 3;
            int gg = lane >> 2, tt = lane & 3;
            int row = mt * 16 + (aidx & 1) * 8 + gg;
            int kk = ks * 8 + (aidx >> 1) * 4 + tt;
            uint32_t v = (row < maxrow) ? src[(size_t)row * stride + kk] : 0u;
            Tf[(c * 32 + lane) * 4 + aidx] = v;
        }
    }
}

__global__ void __launch_bounds__(512, 1)
attn_mma_kernel(const float* __restrict__ tau_ptr) {
    extern __shared__ float sm[];
    float*    e_s = sm;                          // 512*68
    uint32_t* Qf  = (uint32_t*)(e_s + 512 * LDE); // 4096
    uint32_t* Tf  = Qf + 4096;                   // 16384
    float* uks  = (float*)(Tf + 16384);          // 512
    float* vrs  = uks + 512;                     // 576
    float* red  = vrs + 576;                     // 512
    float* rowm = red + 512;                     // 64
    float* rowl = rowm + 64;                     // 64

    const int bh = blockIdx.y, h = bh & 7, b = bh >> 3;
    const int i0 = blockIdx.x * 64;
    const int tid = threadIdx.x, lane = tid & 31, wid = tid >> 5;
    const int gi = lane >> 2, ti = lane & 3;
    const int wm = wid >> 1, wn = wid & 1;        // AC/BD warp grid 8x2

    // ---- init: Q -> B-frag layout; uk/vr slices ----
    {
        const uint32_t* qg = (const uint32_t*)g_q + ((size_t)bh * TT + i0) * 64;
        for (int s = tid; s < 4096; s += 512) {
            int bidx = s & 1, l = (s >> 1) & 31, ks = (s >> 6) & 7, nt = s >> 9;
            int gg = l >> 2, tt = l & 3;
            int ii = nt * 8 + gg;
            int dh = ks * 8 + bidx * 4 + tt;
            Qf[s] = qg[ii * 64 + dh];
        }
        for (int s = tid; s < 512; s += 512) uks[s] = g_uk[bh * 512 + s];
        for (int s = tid; s < 576; s += 512) {
            int u = i0 + s;
            vrs[s] = (u < RR) ? g_vr[u * 8 + h] : 0.f;
        }
    }
    __syncthreads();

    // ---- Phase AC (writes '='): 2 chunks of 256 j-rows ----
    for (int jc = 0; jc < 2; ++jc) {
        stage_A(Tf, (const uint32_t*)g_k + ((size_t)bh * TT + jc * 256) * 64,
                64, 256, 16, wid, lane);
        __syncthreads();

        float c_[2][4][4] = {};
#pragma unroll
        for (int ks = 0; ks < 8; ++ks) {
            uint32_t a[2][4];
#pragma unroll
            for (int m = 0; m < 2; ++m) {
                int mt = wm * 2 + m;
                uint4 v = *(const uint4*)&Tf[((mt * 8 + ks) * 32 + lane) * 4];
                a[m][0] = v.x; a[m][1] = v.y; a[m][2] = v.z; a[m][3] = v.w;
            }
#pragma unroll
            for (int n = 0; n < 4; ++n) {
                int nt = wn * 4 + n;
                uint2 bv = *(const uint2*)&Qf[((nt * 8 + ks) * 32 + lane) * 2];
                uint32_t bb[2] = {bv.x, bv.y};
                mma8(c_[0][n], a[0], bb);
                mma8(c_[1][n], a[1], bb);
            }
        }
#pragma unroll
        for (int m = 0; m < 2; ++m) {
            int j = jc * 256 + wm * 32 + m * 16 + gi;
#pragma unroll
            for (int n = 0; n < 4; ++n) {
                int ii = wn * 32 + n * 8 + 2 * ti;
                *(float2*)&e_s[j * LDE + ii]       = make_float2(c_[m][n][0], c_[m][n][1]);
                *(float2*)&e_s[(j + 8) * LDE + ii] = make_float2(c_[m][n][2], c_[m][n][3]);
            }
        }
        __syncthreads();
    }

    // ---- Phase BD (+=): 3 chunks of 256 u-rows (chunk 2 only 64 useful) ----
    for (int ch = 0; ch < 3; ++ch) {
        int ubase = i0 + ch * 256;
        int maxrow = RR - ubase; if (maxrow > 256) maxrow = 256;
        int tilecap = (ch == 2) ? 4 : 16;
        stage_A(Tf, (const uint32_t*)g_rpe + (size_t)ubase * 512 + h * 64,
                512, maxrow, tilecap, wid, lane);
        __syncthreads();

        if (!(ch == 2 && wm >= 2)) {
            float c_[2][4][4] = {};
#pragma unroll
            for (int ks = 0; ks < 8; ++ks) {
                uint32_t a[2][4];
#pragma unroll
                for (int m = 0; m < 2; ++m) {
                    int mt = wm * 2 + m;
                    uint4 v = *(const uint4*)&Tf[((mt * 8 + ks) * 32 + lane) * 4];
                    a[m][0] = v.x; a[m][1] = v.y; a[m][2] = v.z; a[m][3] = v.w;
                }
#pragma unroll
                for (int n = 0; n < 4; ++n) {
                    int nt = wn * 4 + n;
                    uint2 bv = *(const uint2*)&Qf[((nt * 8 + ks) * 32 + lane) * 2];
                    uint32_t bb[2] = {bv.x, bv.y};
                    mma8(c_[0][n], a[0], bb);
                    mma8(c_[1][n], a[1], bb);
                }
            }
#pragma unroll
            for (int m = 0; m < 2; ++m) {
                int uloc = ch * 256 + wm * 32 + m * 16 + gi;   // u - i0
#pragma unroll
                for (int n = 0; n < 4; ++n) {
                    int ii = wn * 32 + n * 8 + 2 * ti;
                    int j0 = ii - uloc + 511;
                    int j1 = j0 + 1;
                    int j2 = j0 - 8;
                    int j3 = j1 - 8;
                    if ((unsigned)j0 < 512u) e_s[j0 * LDE + ii]     += c_[m][n][0];
                    if ((unsigned)j1 < 512u) e_s[j1 * LDE + ii + 1] += c_[m][n][1];
                    if ((unsigned)j2 < 512u) e_s[j2 * LDE + ii]     += c_[m][n][2];
                    if ((unsigned)j3 < 512u) e_s[j3 * LDE + ii + 1] += c_[m][n][3];
                }
            }
        }
        __syncthreads();
    }

    // ---- finalize + softmax over j, per column i ----
    {
        const float scale = 0.125f;
        const float tauf = expf(tau_ptr[0]);
        int col = tid & 63, seg = tid >> 6;
        int ig = i0 + col;
        float mloc = -FLT_MAX;
        for (int jj = 0; jj < 64; ++jj) {
            int j = seg * 64 + jj;
            float val = e_s[j * LDE + col];
            val = (val + uks[j] + vrs[col - j + 511]) * scale;
            if (j == ig) val = -FLT_MAX;
            val *= tauf;
            e_s[j * LDE + col] = val;
            mloc = fmaxf(mloc, val);
        }
        red[seg * 64 + col] = mloc;
        __syncthreads();
        if (tid < 64) {
            float m = red[tid];
#pragma unroll
            for (int s = 1; s < 8; ++s) m = fmaxf(m, red[s * 64 + tid]);
            rowm[tid] = m;
        }
        __syncthreads();
        float m = rowm[col];
        float sloc = 0.f;
        for (int jj = 0; jj < 64; ++jj) {
            int j = seg * 64 + jj;
            float p = __expf(e_s[j * LDE + col] - m);
            e_s[j * LDE + col] = p;
            sloc += p;
        }
        red[seg * 64 + col] = sloc;
        __syncthreads();
        if (tid < 64) {
            float s = 0.f;
#pragma unroll
            for (int ss = 0; ss < 8; ++ss) s += red[ss * 64 + tid];
            rowl[tid] = s;
        }
        __syncthreads();
    }

    // ---- Phase PV: O[i][dh] = P @ V.  A = P (e_s raw bits), B = V (B-frag) ----
    float o_[2][4] = {};
    const int pwm = wid >> 2;       // i-tile 0..3
    const int pwn = wid & 3;        // dh group 0..3
    const uint32_t* es_u = (const uint32_t*)e_s;
    for (int jc = 0; jc < 2; ++jc) {
        // stage V chunk (256 rows) into B-frag layout in Tf
        const uint32_t* vsrc = (const uint32_t*)g_v + ((size_t)bh * TT + jc * 256) * 64;
#pragma unroll
        for (int k = 0; k < 16; ++k) {
            int c2 = wid + (k << 4);            // c2 = nt*32 + ks
            int nt = c2 >> 5, ks = c2 & 31;
#pragma unroll
            for (int r = 0; r < 2; ++r) {
                int bidx = ((lane >> 4) + r) & 1;
                int gg = lane >> 2, tt = lane & 3;
                int dh = nt * 8 + gg;
                int j = ks * 8 + bidx * 4 + tt;
                Tf[(c2 * 32 + lane) * 2 + bidx] = vsrc[(size_t)j * 64 + dh];
            }
        }
        __syncthreads();

#pragma unroll 4
        for (int ks = 0; ks < 32; ++ks) {
            int jb = jc * 256 + ks * 8;
            int ibase = pwm * 16 + gi;
            uint32_t a[4];
            a[0] = es_u[(jb + ti) * LDE + ibase];
            a[1] = es_u[(jb + ti) * LDE + ibase + 8];
            a[2] = es_u[(jb + ti + 4) * LDE + ibase];
            a[3] = es_u[(jb + ti + 4) * LDE + ibase + 8];
#pragma unroll
            for (int n = 0; n < 2; ++n) {
                int nt = pwn * 2 + n;
                uint2 bv = *(const uint2*)&Tf[((nt * 32 + ks) * 32 + lane) * 2];
                uint32_t bb[2] = {bv.x, bv.y};
                mma8(o_[n], a, bb);
            }
        }
        __syncthreads();
    }

    {
        int i1 = pwm * 16 + gi, i2 = i1 + 8;
        float inv1 = 1.f / rowl[i1];
        float inv2 = 1.f / rowl[i2];
#pragma unroll
        for (int n = 0; n < 2; ++n) {
            int dh = pwn * 16 + n * 8 + 2 * ti;
            float* o1 = g_ao + (size_t)(i0 + i1) * (BB * DD) + b * DD + h * 64 + dh;
            float* o2 = g_ao + (size_t)(i0 + i2) * (BB * DD) + b * DD + h * 64 + dh;
            *(float2*)o1 = make_float2(o_[n][0] * inv1, o_[n][1] * inv1);
            *(float2*)o2 = make_float2(o_[n][2] * inv2, o_[n][3] * inv2);
        }
    }
}

// ============================================================================
// Output projection: out(4096,512) = g_ao @ W_out + b_out (tf32 mma)
// ============================================================================
__global__ void __launch_bounds__(256)
out_mma_kernel(const float* __restrict__ W,
               const float* __restrict__ bias,
               float* __restrict__ out) {
    __shared__ uint32_t As[128 * 36];
    __shared__ uint32_t Bs[32 * 68];
    const int m0 = blockIdx.y * 128, n0 = blockIdx.x * 64;
    const int tid = threadIdx.x, lane = tid & 31, wid = tid >> 5;
    const int gi = lane >> 2, ti = lane & 3;
    const int wm = wid >> 1, wn = wid & 1;

    float c_[2][4][4] = {};

    for (int k0 = 0; k0 < 512; k0 += 32) {
#pragma unroll
        for (int rep = 0; rep < 4; ++rep) {
            int s = rep * 256 + tid;
            int row = s >> 3, kseg = s & 7;
            float4 v = *(const float4*)&g_ao[(size_t)(m0 + row) * 512 + k0 + kseg * 4];
            uint32_t* d = &As[row * 36 + kseg * 4];
            d[0] = f2tf(v.x); d[1] = f2tf(v.y); d[2] = f2tf(v.z); d[3] = f2tf(v.w);
        }
#pragma unroll
        for (int rep = 0; rep < 2; ++rep) {
            int s = rep * 256 + tid;
            int row = s >> 4, nseg = s & 15;
            float4 v = *(const float4*)&W[(size_t)(k0 + row) * 512 + n0 + nseg * 4];
            uint32_t* d = &Bs[row * 68 + nseg * 4];
            d[0] = f2tf(v.x); d[1] = f2tf(v.y); d[2] = f2tf(v.z); d[3] = f2tf(v.w);
        }
        __syncthreads();
#pragma unroll
        for (int kb = 0; kb < 32; kb += 8) {
            uint32_t a[2][4];
#pragma unroll
            for (int mt = 0; mt < 2; ++mt) {
                int r = wm * 32 + mt * 16 + gi;
                a[mt][0] = As[r * 36 + kb + ti];
                a[mt][1] = As[(r + 8) * 36 + kb + ti];
                a[mt][2] = As[r * 36 + kb + ti + 4];
                a[mt][3] = As[(r + 8) * 36 + kb + ti + 4];
            }
#pragma unroll
            for (int nt = 0; nt < 4; ++nt) {
                uint32_t bf[2];
                int ncol = wn * 32 + nt * 8 + gi;
                bf[0] = Bs[(kb + ti) * 68 + ncol];
                bf[1] = Bs[(kb + ti + 4) * 68 + ncol];
                mma8(c_[0][nt], a[0], bf);
                mma8(c_[1][nt], a[1], bf);
            }
        }
        __syncthreads();
    }

#pragma unroll
    for (int mt = 0; mt < 2; ++mt) {
        int m = m0 + wm * 32 + mt * 16 + gi;
#pragma unroll
        for (int nt = 0; nt < 4; ++nt) {
            int n = n0 + wn * 32 + nt * 8 + 2 * ti;
            float b0 = bias[n], b1 = bias[n + 1];
            *(float2*)&out[(size_t)m * 512 + n] =
                make_float2(c_[mt][nt][0] + b0, c_[mt][nt][1] + b1);
            *(float2*)&out[(size_t)(m + 8) * 512 + n] =
                make_float2(c_[mt][nt][2] + b0, c_[mt][nt][3] + b1);
        }
    }
}

// ============================================================================
extern "C" void kernel_launch(void* const* d_in, const int* in_sizes, int n_in,
                              void* d_out, int out_size) {
    const float* x     = (const float*)d_in[0];
    const float* Wqkv  = (const float*)d_in[1];
    const float* Wpos  = (const float*)d_in[2];
    const float* pos_u = (const float*)d_in[3];
    const float* pos_v = (const float*)d_in[4];
    const float* Wout  = (const float*)d_in[5];
    const float* bout  = (const float*)d_in[6];
    const float* ltau  = (const float*)d_in[7];
    float* out = (float*)d_out;

    qkv_mma_kernel<<<dim3(12, 32), 256>>>(x, Wqkv);
    rpe_mma_kernel<<<dim3(8, 8), 256>>>(Wpos);
    uk_kernel<<<128, 256>>>(pos_u);
    vr_kernel<<<32, 256>>>(pos_v);

    const size_t smem = (size_t)(512 * LDE + 4096 + 16384 + 512 + 576 + 512 + 64 + 64) * sizeof(float);
    cudaFuncSetAttribute(attn_mma_kernel, cudaFuncAttributeMaxDynamicSharedMemorySize, (int)smem);
    attn_mma_kernel<<<dim3(8, 64), 512, smem>>>(ltau);

    out_mma_kernel<<<dim3(8, 32), 256>>>(Wout, bout, out);
}